// round 9
// baseline (speedup 1.0000x reference)
#include <cuda_runtime.h>
#include <cuda_bf16.h>

#define B_DIM 4
#define S_DIM 4096
#define F_DIM 512
#define D_DIM 64
#define EGRID 608
#define TOTAL_JOBS 16384   // 256 i-blocks(64) x 64 j-tiles(64)

// ---------------- scratch (no cudaMalloc allowed) ----------------
__device__ __nv_bfloat16 g_Qhi[B_DIM * S_DIM * D_DIM];
__device__ __nv_bfloat16 g_Qlo[B_DIM * S_DIM * D_DIM];
// K in fragment-major layout: 512 j-groups(32 rows) x 4 ks x 2 halves x 512B
__device__ unsigned char g_Kfh[512 * 4096];
__device__ unsigned char g_Kfl[512 * 4096];
__device__ unsigned char g_Whs[8 * 16384];   // pre-swizzled W hi tiles
__device__ unsigned char g_Wls[8 * 16384];   // pre-swizzled W lo tiles

typedef unsigned long long u64;
typedef unsigned u32;

__device__ __forceinline__ float fast_rcp(float x) {
    float r; asm("rcp.approx.f32 %0, %1;" : "=f"(r) : "f"(x)); return r;
}
__device__ __forceinline__ u32 smem_u32(const void* p) {
    u32 a;
    asm("{ .reg .u64 t; cvta.to.shared.u64 t, %1; cvt.u32.u64 %0, t; }" : "=r"(a) : "l"(p));
    return a;
}
__device__ __forceinline__ void ldsm_x4(u32& r0, u32& r1, u32& r2, u32& r3, u32 addr) {
    asm volatile("ldmatrix.sync.aligned.m8n8.x4.shared.b16 {%0,%1,%2,%3}, [%4];"
                 : "=r"(r0), "=r"(r1), "=r"(r2), "=r"(r3) : "r"(addr));
}
__device__ __forceinline__ void mma16816(float* c, const u32* a, const u32* b) {
    asm volatile(
        "mma.sync.aligned.m16n8k16.row.col.f32.bf16.bf16.f32 "
        "{%0,%1,%2,%3}, {%4,%5,%6,%7}, {%8,%9}, {%0,%1,%2,%3};"
        : "+f"(c[0]), "+f"(c[1]), "+f"(c[2]), "+f"(c[3])
        : "r"(a[0]), "r"(a[1]), "r"(a[2]), "r"(a[3]), "r"(b[0]), "r"(b[1]));
}
__device__ __forceinline__ void cp16(u32 dst, const void* src) {
    asm volatile("cp.async.cg.shared.global [%0], [%1], 16;" :: "r"(dst), "l"(src));
}
__device__ __forceinline__ void cp_commit() { asm volatile("cp.async.commit_group;" ::: "memory"); }
__device__ __forceinline__ void cp_wait0()  { asm volatile("cp.async.wait_group 0;" ::: "memory"); }
__device__ __forceinline__ void cp_wait1()  { asm volatile("cp.async.wait_group 1;" ::: "memory"); }

__device__ __forceinline__ void split2(float x, float y, u32& h, u32& l) {
    __nv_bfloat162 hh = __floats2bfloat162_rn(x, y);
    float rx = x - __bfloat162float(hh.x);
    float ry = y - __bfloat162float(hh.y);
    __nv_bfloat162 ll = __floats2bfloat162_rn(rx, ry);
    h = *(u32*)&hh; l = *(u32*)&ll;
}

// =================================================================
// W setup: split Wq|Wk to bf16 hi/lo pre-swizzled tile images
// =================================================================
__global__ __launch_bounds__(256) void wsetup_kernel(
    const float* __restrict__ Wq, const float* __restrict__ Wk)
{
    int idx = blockIdx.x * 256 + threadIdx.x;   // 8192 items
    int c = idx >> 10;
    int j = (idx >> 3) & 127;
    int a = idx & 7;
    const float* wp = (j < 64) ? (Wq + j) : (Wk + (j - 64));
    int f0 = c * 64 + a * 8;
    float wv[8];
    #pragma unroll
    for (int k = 0; k < 8; ++k) wv[k] = wp[(size_t)(f0 + k) * D_DIM];
    uint4 H, L;
    split2(wv[0], wv[1], H.x, L.x);
    split2(wv[2], wv[3], H.y, L.y);
    split2(wv[4], wv[5], H.z, L.z);
    split2(wv[6], wv[7], H.w, L.w);
    u32 off = (u32)j * 128 + (u32)a * 16;
    u32 swo = off ^ ((off >> 3) & 0x70);
    *(uint4*)(g_Whs + c * 16384 + swo) = H;
    *(uint4*)(g_Wls + c * 16384 + swo) = L;
}

// =================================================================
// proj: 64-row tiles, grid 256, 2 CTAs/SM. HMMA [64] x [128 = Q|K].
// Q written row-major (for energy's smem/ldsm A path); K written
// directly in fragment-major layout for energy's LDG B path.
// =================================================================
#define P_FHI 0
#define P_FLO 8192
#define P_W   16384
#define P_WCS 81920
#define P_CHR 82432
#define P_SMEM 82944

__global__ __launch_bounds__(256, 2) void proj_kernel(
    const float* __restrict__ feat, const float* __restrict__ wch,
    const float* __restrict__ bch, const float* __restrict__ loc_p)
{
    extern __shared__ char smem[];
    const u32 sb = smem_u32(smem);
    float* wcs   = (float*)(smem + P_WCS);
    float* chRow = (float*)(smem + P_CHR);

    const int t = threadIdx.x;
    const int wid = t >> 5, lid = t & 31;
    const int wm = wid & 1, wn = wid >> 1;
    const int rowBase = blockIdx.x * 64;

    const int fr = t >> 2, ffo = (t & 3) * 16;
    const int watom = t * 16;

    if (t < 64) wcs[t] = wch[t];

    const u32 lxor  = ((u32)(lid & 7)) << 4;
    const u32 abase = (u32)((wm * 32) + (lid & 7) + ((lid >> 3) & 1) * 8) * 128;
    const u32 ach   = ((u32)(lid >> 4) & 1) * 16;
    const u32 bbase4 = (u32)((wn * 32) + ((lid >> 4) & 1) * 8 + (lid & 7)) * 128;
    const u32 bk4    = ((u32)(lid >> 3) & 1) * 16;

    float acc[2][4][4] = {};
    float csum = 0.f;

    // prefetch W chunk 0 into buf 0
    {
        u32 wb = sb + P_W;
        #pragma unroll
        for (int a = 0; a < 4; ++a) {
            cp16(wb + watom + a * 4096, g_Whs + watom + a * 4096);
            cp16(wb + 16384 + watom + a * 4096, g_Wls + watom + a * 4096);
        }
        cp_commit();
    }

    for (int c = 0; c < 8; ++c) {
        const int f0 = c * 64;
        const u32 wb = sb + P_W + (c & 1) * 32768;
        __syncthreads();
        const float* wc_cur = wcs + (c & 1) * 64;
        {
            const float* fp = feat + (size_t)(rowBase + fr) * F_DIM + f0 + ffo;
            #pragma unroll
            for (int a = 0; a < 2; ++a) {
                float4 v0 = *(const float4*)(fp + a * 8);
                float4 v1 = *(const float4*)(fp + a * 8 + 4);
                csum += v0.x * wc_cur[ffo + a*8 + 0] + v0.y * wc_cur[ffo + a*8 + 1]
                      + v0.z * wc_cur[ffo + a*8 + 2] + v0.w * wc_cur[ffo + a*8 + 3]
                      + v1.x * wc_cur[ffo + a*8 + 4] + v1.y * wc_cur[ffo + a*8 + 5]
                      + v1.z * wc_cur[ffo + a*8 + 6] + v1.w * wc_cur[ffo + a*8 + 7];
                uint4 H, L;
                split2(v0.x, v0.y, H.x, L.x);
                split2(v0.z, v0.w, H.y, L.y);
                split2(v1.x, v1.y, H.z, L.z);
                split2(v1.z, v1.w, H.w, L.w);
                u32 off = (u32)fr * 128 + (u32)(ffo + a * 8) * 2;
                u32 swo = off ^ ((off >> 3) & 0x70);
                *(uint4*)(smem + P_FHI + swo) = H;
                *(uint4*)(smem + P_FLO + swo) = L;
            }
        }
        if (c + 1 < 8) {
            u32 nwb = sb + P_W + ((c + 1) & 1) * 32768;
            const unsigned char* gh = g_Whs + (c + 1) * 16384;
            const unsigned char* gl = g_Wls + (c + 1) * 16384;
            #pragma unroll
            for (int a = 0; a < 4; ++a) {
                cp16(nwb + watom + a * 4096, gh + watom + a * 4096);
                cp16(nwb + 16384 + watom + a * 4096, gl + watom + a * 4096);
            }
            cp_commit();
            cp_wait1();
        } else {
            cp_wait0();
        }
        if (t < 64 && c + 1 < 8) wcs[((c + 1) & 1) * 64 + t] = wch[f0 + 64 + t];
        __syncthreads();

        #pragma unroll
        for (int ks = 0; ks < 4; ++ks) {
            const u32 akb = ((u32)(ks * 32) + ach) ^ lxor;
            const u32 bkb = ((u32)(ks * 32) + bk4) ^ lxor;
            u32 afH[2][4], afL[2][4], bH[8], bL[8];
            #pragma unroll
            for (int mt = 0; mt < 2; ++mt)
                ldsm_x4(afH[mt][0], afH[mt][1], afH[mt][2], afH[mt][3],
                        sb + P_FHI + abase + mt * 2048 + akb);
            ldsm_x4(bH[0], bH[1], bH[2], bH[3], wb + bbase4 + bkb);
            ldsm_x4(bH[4], bH[5], bH[6], bH[7], wb + bbase4 + 2048 + bkb);
            #pragma unroll
            for (int mt = 0; mt < 2; ++mt)
                #pragma unroll
                for (int nt = 0; nt < 4; ++nt)
                    mma16816(acc[mt][nt], afH[mt], bH + nt * 2);
            ldsm_x4(bL[0], bL[1], bL[2], bL[3], wb + 16384 + bbase4 + bkb);
            ldsm_x4(bL[4], bL[5], bL[6], bL[7], wb + 16384 + bbase4 + 2048 + bkb);
            #pragma unroll
            for (int mt = 0; mt < 2; ++mt)
                #pragma unroll
                for (int nt = 0; nt < 4; ++nt)
                    mma16816(acc[mt][nt], afH[mt], bL + nt * 2);
            #pragma unroll
            for (int mt = 0; mt < 2; ++mt)
                ldsm_x4(afL[mt][0], afL[mt][1], afL[mt][2], afL[mt][3],
                        sb + P_FLO + abase + mt * 2048 + akb);
            #pragma unroll
            for (int mt = 0; mt < 2; ++mt)
                #pragma unroll
                for (int nt = 0; nt < 4; ++nt)
                    mma16816(acc[mt][nt], afL[mt], bH + nt * 2);
        }
    }

    csum += __shfl_xor_sync(0xffffffffu, csum, 1);
    csum += __shfl_xor_sync(0xffffffffu, csum, 2);
    if ((t & 3) == 0) chRow[fr] = 1.f / (1.f + expf(-(csum + bch[0])));
    __syncthreads();

    const float nls = -0.125f * loc_p[0];
    const int g = lid >> 2, tg = lid & 3;
    #pragma unroll
    for (int mt = 0; mt < 2; ++mt) {
        #pragma unroll
        for (int half = 0; half < 2; ++half) {
            int il = wm * 32 + mt * 16 + g + half * 8;
            size_t row = (size_t)(rowBase + il);
            float cr = chRow[il];
            #pragma unroll
            for (int nt = 0; nt < 4; ++nt) {
                int jl = wn * 32 + nt * 8 + tg * 2;
                float sc = (jl < 64) ? (nls * cr) : cr;
                float c0 = acc[mt][nt][half * 2 + 0] * sc;
                float c1 = acc[mt][nt][half * 2 + 1] * sc;
                u32 h, l;
                split2(c0, c1, h, l);
                if (jl < 64) {
                    *(u32*)&g_Qhi[row * D_DIM + jl] = h;
                    *(u32*)&g_Qlo[row * D_DIM + jl] = l;
                } else {
                    // K -> fragment-major layout
                    int dl  = jl - 64;
                    int grp = (int)(row >> 5);
                    int r   = (int)(row & 31);
                    int ntf = r >> 3;
                    int dk  = dl & 15;
                    int p   = (dk >= 8) ? ((dk - 8) >> 1) : (dk >> 1);
                    int lane = ((r & 7) << 2) | p;
                    int ks   = dl >> 4;
                    int hi4  = (dk >= 8) ? 4 : 0;
                    size_t addr = ((size_t)((grp * 4 + ks) * 2 + (ntf >> 1))) * 512
                                  + (size_t)lane * 16 + (ntf & 1) * 8 + hi4;
                    *(u32*)(g_Kfh + addr) = h;
                    *(u32*)(g_Kfl + addr) = l;
                }
            }
        }
    }
}

// =================================================================
// energy: persistent, 4 CTAs/SM (128 threads), job tile 64(i) x 64(j)
// A-hi fragments hoisted per i-block; B fragments via coalesced LDG
// from fragment-major K (register double-buffered). NO per-job syncs.
// smem: Qhi 0(8K), Qlo 8K — 16KB total.
// =================================================================
#define E_SMEM 16384

__global__ __launch_bounds__(128, 4) void energy_kernel(float* __restrict__ out)
{
    extern __shared__ char smem[];
    const u32 sb = smem_u32(smem);

    const int t = threadIdx.x;
    const int wid = t >> 5, lid = t & 31;
    const int wm = wid & 1, wn = wid >> 1;

    const int js = (int)(((long long)blockIdx.x * TOTAL_JOBS) / EGRID);
    const int je = (int)(((long long)(blockIdx.x + 1) * TOTAL_JOBS) / EGRID);

    const int lc16 = t & 7;
    const int row16 = t >> 3;     // + 16*l

    const u32 lxor  = ((u32)(lid & 7)) << 4;
    const u32 abase = (u32)((wm * 32) + (lid & 7) + ((lid >> 3) & 1) * 8) * 128;
    const u32 ach   = ((u32)(lid >> 4) & 1) * 16;

    int curIb = -1;
    u32 afH[4][2][4];   // hoisted A-hi fragments
    u32 bh[2][8];       // B-hi double buffer (across ks and jobs)
    u32 bl[8];          // B-lo single buffer

    // cold-start: load bh for first job, ks=0
    {
        int ib0 = js >> 6;
        int jg0 = (ib0 >> 6) * 128 + (js & 63) * 2 + wn;
        const unsigned char* p = g_Kfh + (size_t)jg0 * 4096 + (size_t)lid * 16;
        *(uint4*)&bh[0][0] = *(const uint4*)(p);
        *(uint4*)&bh[0][4] = *(const uint4*)(p + 512);
    }

    for (int job = js; job < je; ++job) {
        const int ib = job >> 6;
        const int jt = job & 63;

        if (ib != curIb) {
            __syncthreads();
            size_t qrow0 = (size_t)ib * 64;
            #pragma unroll
            for (int l = 0; l < 4; ++l) {
                int row = row16 + 16 * l;
                u32 off = (u32)row * 128 + (u32)lc16 * 16;
                u32 swo = off ^ ((off >> 3) & 0x70);
                *(uint4*)(smem + swo) =
                    *(const uint4*)((const char*)(g_Qhi + (qrow0 + row) * D_DIM) + lc16 * 16);
                *(uint4*)(smem + 8192 + swo) =
                    *(const uint4*)((const char*)(g_Qlo + (qrow0 + row) * D_DIM) + lc16 * 16);
            }
            curIb = ib;
            __syncthreads();
            #pragma unroll
            for (int ks = 0; ks < 4; ++ks) {
                const u32 akb = ((u32)(ks * 32) + ach) ^ lxor;
                #pragma unroll
                for (int mt = 0; mt < 2; ++mt)
                    ldsm_x4(afH[ks][mt][0], afH[ks][mt][1], afH[ks][mt][2], afH[ks][mt][3],
                            sb + abase + mt * 2048 + akb);
            }
        }

        const int jg = (ib >> 6) * 128 + jt * 2 + wn;
        const unsigned char* bp_h = g_Kfh + (size_t)jg * 4096 + (size_t)lid * 16;
        const unsigned char* bp_l = g_Kfl + (size_t)jg * 4096 + (size_t)lid * 16;
        // next job's bh ks0 pointer (prefetched during ks==3)
        const int jobn = (job + 1 < je) ? (job + 1) : job;
        const int jgn = ((jobn >> 6) >> 6) * 128 + (jobn & 63) * 2 + wn;
        const unsigned char* bpn_h = g_Kfh + (size_t)jgn * 4096 + (size_t)lid * 16;

        float acc[2][4][4] = {};
        #pragma unroll
        for (int ks = 0; ks < 4; ++ks) {
            const int cur = ks & 1, nxt = cur ^ 1;
            // load B-lo for this ks (used after pass1)
            *(uint4*)&bl[0] = *(const uint4*)(bp_l + ks * 1024);
            *(uint4*)&bl[4] = *(const uint4*)(bp_l + ks * 1024 + 512);
            // prefetch B-hi for next ks (or next job's ks0)
            {
                const unsigned char* pn = (ks < 3) ? (bp_h + (ks + 1) * 1024) : bpn_h;
                *(uint4*)&bh[nxt][0] = *(const uint4*)(pn);
                *(uint4*)&bh[nxt][4] = *(const uint4*)(pn + 512);
            }
            // pass1: Qhi x Khi
            #pragma unroll
            for (int mt = 0; mt < 2; ++mt)
                #pragma unroll
                for (int nt = 0; nt < 4; ++nt)
                    mma16816(acc[mt][nt], afH[ks][mt], &bh[cur][nt * 2]);
            // A-lo fragments for this ks
            u32 aL[2][4];
            {
                const u32 akb = ((u32)(ks * 32) + ach) ^ lxor;
                #pragma unroll
                for (int mt = 0; mt < 2; ++mt)
                    ldsm_x4(aL[mt][0], aL[mt][1], aL[mt][2], aL[mt][3],
                            sb + 8192 + abase + mt * 2048 + akb);
            }
            // pass2: Qhi x Klo
            #pragma unroll
            for (int mt = 0; mt < 2; ++mt)
                #pragma unroll
                for (int nt = 0; nt < 4; ++nt)
                    mma16816(acc[mt][nt], afH[ks][mt], &bl[nt * 2]);
            // pass3: Qlo x Khi
            #pragma unroll
            for (int mt = 0; mt < 2; ++mt)
                #pragma unroll
                for (int nt = 0; nt < 4; ++nt)
                    mma16816(acc[mt][nt], aL[mt], &bh[cur][nt * 2]);
        }

        // ---- epilogue: v * rcp(|i-j|) ----
        const int iPos0 = (ib & 63) * 64;
        const int jj0 = jt * 64;
        const int g = lid >> 2, tg = lid & 3;
        float* ob = out + ((size_t)ib * 64) * S_DIM + jj0;
        #pragma unroll
        for (int mt = 0; mt < 2; ++mt) {
            #pragma unroll
            for (int half = 0; half < 2; ++half) {
                int il = wm * 32 + mt * 16 + g + half * 8;
                int ip = iPos0 + il;
                float* orow = ob + (size_t)il * S_DIM;
                #pragma unroll
                for (int nt = 0; nt < 4; ++nt) {
                    int jl = wn * 32 + nt * 8 + tg * 2;
                    int jp = jj0 + jl;
                    float d0 = fmaxf(fabsf((float)(ip - jp)), 1.f);
                    float d1 = fmaxf(fabsf((float)(ip - jp - 1)), 1.f);
                    float2 o;
                    o.x = acc[mt][nt][half * 2 + 0] * fast_rcp(d0);
                    o.y = acc[mt][nt][half * 2 + 1] * fast_rcp(d1);
                    *(float2*)(orow + jl) = o;
                }
            }
        }
    }
}

extern "C" void kernel_launch(void* const* d_in, const int* in_sizes, int n_in,
                              void* d_out, int out_size) {
    const float* feat = (const float*)d_in[0];
    const float* Wq   = (const float*)d_in[1];
    const float* Wk   = (const float*)d_in[2];
    const float* wch  = (const float*)d_in[3];
    const float* bch  = (const float*)d_in[4];
    const float* ls   = (const float*)d_in[5];
    float* out = (float*)d_out;

    cudaFuncSetAttribute(proj_kernel, cudaFuncAttributeMaxDynamicSharedMemorySize, P_SMEM);

    wsetup_kernel<<<32, 256>>>(Wq, Wk);
    proj_kernel<<<(B_DIM * S_DIM) / 64, 256, P_SMEM>>>(feat, wch, bch, ls);
    energy_kernel<<<EGRID, 128, E_SMEM>>>(out);
}